// round 2
// baseline (speedup 1.0000x reference)
#include <cuda_runtime.h>
#include <math.h>
#include <float.h>

// Temporal Contrast Enhancement (Weger et al. 2019) as three cascaded
// max/min-affine parallel scans.
//
//   envd:  y[t] = max(x[t], (1-ad)*x[t] + ad*y[t-1])   (smooth decay)
//   enva:  y[t] = min(x[t], (1-aa)*x[t] + aa*y[t-1])   (smooth attack)
//
// Maps y -> op(U, A*y + V) (A>0) compose associatively:
//   (b after a): U' = op(bU, bA*aU + bV); A' = bA*aA; V' = bA*aV + bV
// so each follower is a parallel scan. Exact (no truncation approximation).

#define THREADS 512
#define RPT 8
#define CHUNK (THREADS * RPT)   // 4096
#define NWARPS (THREADS / 32)   // 16
#define T_LEN 88200

struct Tf { float U, A, V; };

template <bool MAXOP>
__device__ __forceinline__ float sel(float a, float b) {
    return MAXOP ? fmaxf(a, b) : fminf(a, b);
}

template <bool MAXOP>
__device__ __forceinline__ Tf tf_id() {
    Tf r; r.U = MAXOP ? -FLT_MAX : FLT_MAX; r.A = 1.0f; r.V = 0.0f; return r;
}

// Compose: b applied after a.
template <bool MAXOP>
__device__ __forceinline__ Tf tf_comb(Tf a, Tf b) {
    Tf r;
    r.U = sel<MAXOP>(b.U, fmaf(b.A, a.U, b.V));
    r.A = b.A * a.A;
    r.V = fmaf(b.A, a.V, b.V);
    return r;
}

__device__ __forceinline__ Tf tf_shflup(Tf t, int d) {
    Tf r;
    r.U = __shfl_up_sync(0xffffffffu, t.U, d);
    r.A = __shfl_up_sync(0xffffffffu, t.A, d);
    r.V = __shfl_up_sync(0xffffffffu, t.V, d);
    return r;
}

// One block-level scan over the current chunk. m: per-thread RPT contiguous
// input samples (registers). out: per-thread outputs (may alias m). carry is
// replicated identically in every thread's registers and updated here.
// All threads (active or not) execute every collective.
template <bool MAXOP>
__device__ __forceinline__ void scan8(const float* m, float* out, float alpha,
                                      bool active, float& carry, Tf* s_warp)
{
    const int lane = threadIdx.x & 31;
    const int wid  = threadIdx.x >> 5;
    const float om = 1.0f - alpha;

    // Per-thread segment compose (inactive threads hold identity)
    Tf loc = tf_id<MAXOP>();
    if (active) {
        #pragma unroll
        for (int j = 0; j < RPT; j++) {
            Tf f; f.U = m[j]; f.A = alpha; f.V = om * m[j];
            loc = tf_comb<MAXOP>(loc, f);
        }
    }

    // Warp inclusive scan
    Tf inc = loc;
    #pragma unroll
    for (int d = 1; d < 32; d <<= 1) {
        Tf up = tf_shflup(inc, d);
        if (lane >= d) inc = tf_comb<MAXOP>(up, inc);
    }

    __syncthreads();               // WAR: previous scan's readers of s_warp done
    if (lane == 31) s_warp[wid] = inc;
    __syncthreads();

    // Cross-warp scan (warp 0 scans 16 warp totals; pad with identity)
    if (wid == 0) {
        Tf w = (lane < NWARPS) ? s_warp[lane] : tf_id<MAXOP>();
        #pragma unroll
        for (int d = 1; d < 32; d <<= 1) {
            Tf up = tf_shflup(w, d);
            if (lane >= d) w = tf_comb<MAXOP>(up, w);
        }
        if (lane < NWARPS) s_warp[lane] = w;
    }
    __syncthreads();

    // Per-thread exclusive prefix
    Tf exw = tf_shflup(inc, 1);
    if (lane == 0) exw = tf_id<MAXOP>();
    Tf ex = (wid == 0) ? exw : tf_comb<MAXOP>(s_warp[wid - 1], exw);

    // Serial apply within segment
    if (active) {
        float y = sel<MAXOP>(ex.U, fmaf(ex.A, carry, ex.V));
        #pragma unroll
        for (int j = 0; j < RPT; j++) {
            y = sel<MAXOP>(m[j], fmaf(alpha, y, om * m[j]));
            out[j] = y;
        }
    }

    // Update replicated carry from block total (inclusive over all warps)
    Tf tot = s_warp[NWARPS - 1];
    carry = sel<MAXOP>(tot.U, fmaf(tot.A, carry, tot.V));
}

__global__ void __launch_bounds__(THREADS)
tce_kernel(const float* __restrict__ x,
           const float* __restrict__ p_tauA,
           const float* __restrict__ p_tauD,
           const float* __restrict__ p_nu,
           const float* __restrict__ p_dbr,
           float* __restrict__ out, int T)
{
    __shared__ Tf s_warp[NWARPS];

    const long long ch = blockIdx.x;
    const float* xc = x + ch * (long long)T;
    float* oc = out + ch * (long long)T;

    // Scalar params (device-resident; replicate the reference's clip chain)
    float tauA = fminf(fmaxf(p_tauA[0], 1.0f), 100.0f);
    tauA = fminf(fmaxf(tauA, 0.1f), 1000.0f) * 0.001f;
    const float aa = expf(-1.0f / (tauA * 44100.0f));
    float tauD = fminf(fmaxf(p_tauD[0], 1.0f), 100.0f);
    tauD = fminf(fmaxf(tauD, 0.1f), 1000.0f) * 0.001f;
    const float ad = expf(-1.0f / (tauD * 44100.0f));
    const float nuAmp = exp10f(fminf(fmaxf(p_nu[0], -60.0f), 0.0f) * 0.05f);
    const float reg   = exp10f(fminf(fmaxf(p_dbr[0], -120.0f), -60.0f) * 0.05f);

    float cd = 0.0f, ca = 0.0f, ce = 0.0f;   // carries: envd(|x|), enva, envd(et)

    for (int base = 0; base < T; base += CHUNK) {
        const int rem = T - base;
        // Active threads with a FULL 8-sample segment. For T=88200 the tail
        // (2184 = 273*8) divides exactly; the generic guard below tolerates
        // other shapes by serializing a sub-RPT remainder onto one thread.
        const int full = rem / RPT;
        const int nact = min(THREADS, full);
        const bool active = (int)threadIdx.x < nact;

        float xv[RPT], a[RPT], b[RPT];
        if (active) {
            const float4* p = reinterpret_cast<const float4*>(
                xc + base + (int)threadIdx.x * RPT);
            float4 v0 = p[0];
            float4 v1 = p[1];
            xv[0] = v0.x; xv[1] = v0.y; xv[2] = v0.z; xv[3] = v0.w;
            xv[4] = v1.x; xv[5] = v1.y; xv[6] = v1.z; xv[7] = v1.w;
            #pragma unroll
            for (int j = 0; j < RPT; j++) a[j] = fabsf(xv[j]);
        }

        // et_d = envd(|x|)        (max-affine scan, alpha_d)   a -> a
        scan8<true>(a, a, ad, active, cd, s_warp);
        // et_a = enva(et_d)       (min-affine scan, alpha_a)   a -> b
        scan8<false>(a, b, aa, active, ca, s_warp);
        // et = relu(et_d - et_a - nu_amp)                      -> b
        if (active) {
            #pragma unroll
            for (int j = 0; j < RPT; j++)
                b[j] = fmaxf(a[j] - b[j] - nuAmp, 0.0f);
        }
        // et_env = envd(et)       (max-affine scan, alpha_d)   b -> a
        scan8<true>(b, a, ad, active, ce, s_warp);

        // out = x * et / (et_env + reg)
        if (active) {
            float r[RPT];
            #pragma unroll
            for (int j = 0; j < RPT; j++)
                r[j] = xv[j] * b[j] / (a[j] + reg);
            float4* po = reinterpret_cast<float4*>(
                oc + base + (int)threadIdx.x * RPT);
            float4 o0, o1;
            o0.x = r[0]; o0.y = r[1]; o0.z = r[2]; o0.w = r[3];
            o1.x = r[4]; o1.y = r[5]; o1.z = r[6]; o1.w = r[7];
            po[0] = o0;
            po[1] = o1;
        }

        // Generic sub-RPT remainder (never taken for T=88200): serialize the
        // leftover (rem % RPT) samples on thread 0 after the block scans.
        const int extra = (rem < CHUNK) ? (rem - nact * RPT) : 0;
        if (extra > 0 && threadIdx.x == 0) {
            const int s0 = base + nact * RPT;
            float yd = cd, ya = ca, ye = ce;
            for (int j = 0; j < extra; j++) {
                const float xj = xc[s0 + j];
                const float av = fabsf(xj);
                yd = fmaxf(av, fmaf(ad, yd, (1.0f - ad) * av));
                ya = fminf(yd, fmaf(aa, ya, (1.0f - aa) * yd));
                const float et = fmaxf(yd - ya - nuAmp, 0.0f);
                ye = fmaxf(et, fmaf(ad, ye, (1.0f - ad) * et));
                oc[s0 + j] = xj * et / (ye + reg);
            }
        }
    }
}

extern "C" void kernel_launch(void* const* d_in, const int* in_sizes, int n_in,
                              void* d_out, int out_size)
{
    const float* x      = (const float*)d_in[0];
    const float* tauAtc = (const float*)d_in[1];
    const float* tauDtc = (const float*)d_in[2];
    const float* nu     = (const float*)d_in[3];
    const float* dbr    = (const float*)d_in[4];
    float* out = (float*)d_out;

    const int T = T_LEN;
    const int channels = in_sizes[0] / T;   // 8*32 = 256

    tce_kernel<<<channels, THREADS>>>(x, tauAtc, tauDtc, nu, dbr, out, T);
}

// round 4
// speedup vs baseline: 2.2398x; 2.2398x over previous
#include <cuda_runtime.h>
#include <math.h>
#include <float.h>

// Temporal Contrast Enhancement as three cascaded max/min-affine parallel
// scans, v2.1: implicit-A scans, two-scalar phase-1 + carry-seeded fixup,
// redundant cross-warp scan, 1 barrier per scan.
// Fix vs v2: warp-aggregate decay is alpha^512 = (alpha^16)^32, computed by
// five squarings (was erroneously (alpha^16)^2).
//
//   envd:  y[t] = max(x[t], (1-a)*x[t] + a*y[t-1])
//   enva:  y[t] = min(x[t], (1-a)*x[t] + a*y[t-1])
// y -> op(U, A*y + V), A>0 composes associatively. Exact.

#define THREADS 256
#define RPT 16
#define CHUNK (THREADS * RPT)    // 4096
#define NWARPS (THREADS / 32)    // 8
#define T_LEN 88200

template <bool MAXOP>
__device__ __forceinline__ float sel(float a, float b) {
    return MAXOP ? fmaxf(a, b) : fminf(a, b);
}

// Block scan of one chunk. in[RPT] -> out[RPT] (distinct register arrays).
// q = alpha^RPT; qwarp = q^32 = alpha^(RPT*32) (warp aggregate decay);
// qstep[k] = q^min(lane+1,2^k); qlane = q^lane.
// carry: replicated resolved value entering this chunk.
template <bool MAXOP>
__device__ __forceinline__ void scan16(const float* in, float* out,
                                       float alpha, float om, float qwarp,
                                       const float* qstep, float qlane,
                                       float& carry, float2* sw,
                                       int lane, int wid)
{
    // Phase 1: per-thread running linear response v and local envelope yl.
    float v = 0.0f, yl = 0.0f;
    #pragma unroll
    for (int j = 0; j < RPT; j++) {
        float omm = om * in[j];
        if (j == 0) { v = omm; yl = in[0]; }
        else {
            v  = fmaf(alpha, v, omm);
            yl = sel<MAXOP>(in[j], fmaf(alpha, yl, omm));
        }
        out[j] = yl;
    }

    // Warp scan over thread aggregates (U, V); A implicit via qstep.
    float U = yl, V = v;
    #pragma unroll
    for (int k = 0; k < 5; k++) {
        const int d = 1 << k;
        float uU = __shfl_up_sync(0xffffffffu, U, d);
        float uV = __shfl_up_sync(0xffffffffu, V, d);
        float bA = qstep[k];
        if (lane >= d) {
            U = sel<MAXOP>(U, fmaf(bA, uU, V));
            V = fmaf(bA, uV, V);
        }
    }
    // Lane-exclusive transform (A = qlane implicit)
    float Ue = __shfl_up_sync(0xffffffffu, U, 1);
    float Ve = __shfl_up_sync(0xffffffffu, V, 1);

    if (lane == 31) sw[wid] = make_float2(U, V);
    __syncthreads();

    // Cross-warp scan over NWARPS aggregates, redundantly in every warp.
    float cU, cV, cA;
    if (lane < NWARPS) { float2 t = sw[lane]; cU = t.x; cV = t.y; cA = qwarp; }
    else { cU = MAXOP ? -FLT_MAX : FLT_MAX; cV = 0.0f; cA = 1.0f; }
    #pragma unroll
    for (int k = 0; k < 3; k++) {           // NWARPS = 8 -> 3 steps
        const int d = 1 << k;
        float uU = __shfl_up_sync(0xffffffffu, cU, d);
        float uV = __shfl_up_sync(0xffffffffu, cV, d);
        float uA = __shfl_up_sync(0xffffffffu, cA, d);
        if (lane >= d) {
            float nU = sel<MAXOP>(cU, fmaf(cA, uU, cV));
            float nV = fmaf(cA, uV, cV);
            cA = cA * uA; cU = nU; cV = nV;
        }
    }

    // Warp-incoming resolved value c_w = apply(cross_excl[wid], carry)
    const int src = (wid == 0) ? 0 : (wid - 1);
    float WU = __shfl_sync(0xffffffffu, cU, src);
    float WV = __shfl_sync(0xffffffffu, cV, src);
    float WA = __shfl_sync(0xffffffffu, cA, src);
    float c_w = (wid == 0) ? carry : sel<MAXOP>(WU, fmaf(WA, carry, WV));

    // Block-total transform for carry update
    float TU = __shfl_sync(0xffffffffu, cU, NWARPS - 1);
    float TV = __shfl_sync(0xffffffffu, cV, NWARPS - 1);
    float TA = __shfl_sync(0xffffffffu, cA, NWARPS - 1);
    float ncar = sel<MAXOP>(TU, fmaf(TA, carry, TV));

    // Thread-incoming resolved value
    float c = (lane == 0) ? c_w : sel<MAXOP>(Ue, fmaf(qlane, c_w, Ve));

    // Fixup: re-run linear recurrence seeded with c; out = op(local, z).
    float z = c;
    #pragma unroll
    for (int j = 0; j < RPT; j++) {
        z = fmaf(alpha, z, om * in[j]);
        out[j] = sel<MAXOP>(out[j], z);
    }
    carry = ncar;
}

__global__ void __launch_bounds__(THREADS)
tce_kernel(const float* __restrict__ x,
           const float* __restrict__ p_tauA,
           const float* __restrict__ p_tauD,
           const float* __restrict__ p_nu,
           const float* __restrict__ p_dbr,
           float* __restrict__ out, int T)
{
    __shared__ float2 swb[3][NWARPS];

    const int lane = threadIdx.x & 31;
    const int wid  = threadIdx.x >> 5;
    const long long ch = blockIdx.x;
    const float* xc = x + ch * (long long)T;
    float* oc = out + ch * (long long)T;

    // Scalar params (replicate reference clip chain)
    float tauA = fminf(fmaxf(p_tauA[0], 1.0f), 100.0f);
    tauA = fminf(fmaxf(tauA, 0.1f), 1000.0f) * 0.001f;
    const float aa = expf(-1.0f / (tauA * 44100.0f));
    float tauD = fminf(fmaxf(p_tauD[0], 1.0f), 100.0f);
    tauD = fminf(fmaxf(tauD, 0.1f), 1000.0f) * 0.001f;
    const float ad = expf(-1.0f / (tauD * 44100.0f));
    const float nuAmp = exp10f(fminf(fmaxf(p_nu[0], -60.0f), 0.0f) * 0.05f);
    const float reg   = exp10f(fminf(fmaxf(p_dbr[0], -120.0f), -60.0f) * 0.05f);
    const float omd = 1.0f - ad;
    const float oma = 1.0f - aa;

    // q = alpha^16 via 4 squarings; qwarp = q^32 via 5 more squarings.
    float qd = ad * ad; qd *= qd; qd *= qd; qd *= qd;   // ad^16
    float qa = aa * aa; qa *= qa; qa *= qa; qa *= qa;   // aa^16
    float qwd = qd * qd; qwd *= qwd; qwd *= qwd; qwd *= qwd; qwd *= qwd; // qd^32
    float qwa = qa * qa; qwa *= qwa; qwa *= qwa; qwa *= qwa; qwa *= qwa; // qa^32

    // Per-lane power tables (init-only loops).
    float qdstep[5], qastep[5];
    #pragma unroll
    for (int k = 0; k < 5; k++) {
        const int e = min(lane + 1, 1 << k);
        float pd = 1.0f, pa = 1.0f;
        for (int i = 0; i < e; i++) { pd *= qd; pa *= qa; }
        qdstep[k] = pd; qastep[k] = pa;
    }
    float qdlane = 1.0f, qalane = 1.0f;
    for (int i = 0; i < lane; i++) { qdlane *= qd; qalane *= qa; }

    float cd = 0.0f, ca = 0.0f, ce = 0.0f;   // carries

    for (int base = 0; base < T; base += CHUNK) {
        const int off = base + (int)threadIdx.x * RPT;
        float A_[RPT], B_[RPT];

        // Load |x| (zero-padded beyond T; tail chunk only)
        #pragma unroll
        for (int g = 0; g < RPT / 4; g++) {
            const int o = off + g * 4;
            float4 v = make_float4(0.f, 0.f, 0.f, 0.f);
            if (o + 4 <= T) {
                v = *reinterpret_cast<const float4*>(xc + o);
            } else if (o < T) {
                v.x = xc[o];
                if (o + 1 < T) v.y = xc[o + 1];
                if (o + 2 < T) v.z = xc[o + 2];
            }
            A_[4 * g + 0] = fabsf(v.x);
            A_[4 * g + 1] = fabsf(v.y);
            A_[4 * g + 2] = fabsf(v.z);
            A_[4 * g + 3] = fabsf(v.w);
        }

        // et_d = envd(|x|)   (max, alpha_d):  A_ -> B_
        scan16<true >(A_, B_, ad, omd, qwd, qdstep, qdlane, cd, swb[0], lane, wid);
        // et_a = enva(et_d)  (min, alpha_a):  B_ -> A_
        scan16<false>(B_, A_, aa, oma, qwa, qastep, qalane, ca, swb[1], lane, wid);
        // et = relu(et_d - et_a - nuAmp)   -> A_
        #pragma unroll
        for (int j = 0; j < RPT; j++)
            A_[j] = fmaxf(B_[j] - A_[j] - nuAmp, 0.0f);
        // et_env = envd(et)  (max, alpha_d):  A_ -> B_
        scan16<true >(A_, B_, ad, omd, qwd, qdstep, qdlane, ce, swb[2], lane, wid);

        // out = x * et / (et_env + reg)   (x reloaded; L2-hot)
        #pragma unroll
        for (int g = 0; g < RPT / 4; g++) {
            const int o = off + g * 4;
            if (o + 4 <= T) {
                float4 xv = *reinterpret_cast<const float4*>(xc + o);
                float4 r;
                r.x = xv.x * __fdividef(A_[4 * g + 0], B_[4 * g + 0] + reg);
                r.y = xv.y * __fdividef(A_[4 * g + 1], B_[4 * g + 1] + reg);
                r.z = xv.z * __fdividef(A_[4 * g + 2], B_[4 * g + 2] + reg);
                r.w = xv.w * __fdividef(A_[4 * g + 3], B_[4 * g + 3] + reg);
                *reinterpret_cast<float4*>(oc + o) = r;
            } else if (o < T) {
                oc[o] = xc[o] * __fdividef(A_[4 * g + 0], B_[4 * g + 0] + reg);
                if (o + 1 < T)
                    oc[o + 1] = xc[o + 1] * __fdividef(A_[4 * g + 1], B_[4 * g + 1] + reg);
                if (o + 2 < T)
                    oc[o + 2] = xc[o + 2] * __fdividef(A_[4 * g + 2], B_[4 * g + 2] + reg);
            }
        }
    }
}

extern "C" void kernel_launch(void* const* d_in, const int* in_sizes, int n_in,
                              void* d_out, int out_size)
{
    const float* x      = (const float*)d_in[0];
    const float* tauAtc = (const float*)d_in[1];
    const float* tauDtc = (const float*)d_in[2];
    const float* nu     = (const float*)d_in[3];
    const float* dbr    = (const float*)d_in[4];
    float* out = (float*)d_out;

    const int T = T_LEN;
    const int channels = in_sizes[0] / T;   // 256

    tce_kernel<<<channels, THREADS>>>(x, tauAtc, tauDtc, nu, dbr, out, T);
}

// round 5
// speedup vs baseline: 2.5250x; 1.1274x over previous
#include <cuda_runtime.h>
#include <math.h>
#include <float.h>

// Temporal Contrast Enhancement as three cascaded max/min-affine parallel
// scans, v3: 512 threads x 8 samples (same CHUNK=4096), uniform implicit-A
// step factors (q^(2^k) is uniform over combining lanes in Kogge-Stone),
// two-scalar phase-1 + carry-seeded fixup, 1 barrier per scan, grid=channels
// (block imbalance self-balances: warps per SM proportional to work).
//
//   envd:  y[t] = max(x[t], (1-a)*x[t] + a*y[t-1])
//   enva:  y[t] = min(x[t], (1-a)*x[t] + a*y[t-1])
// y -> op(U, A*y + V), A>0 composes associatively. Exact.

#define THREADS 512
#define RPT 8
#define CHUNK (THREADS * RPT)    // 4096
#define NWARPS (THREADS / 32)    // 16
#define T_LEN 88200

template <bool MAXOP>
__device__ __forceinline__ float sel(float a, float b) {
    return MAXOP ? fmaxf(a, b) : fminf(a, b);
}

// Block scan of one chunk. in[RPT] -> out[RPT] (distinct register arrays).
// q = alpha^RPT. qpow[k] = q^(2^k) (uniform). qwarp = q^32; qwpow[k] =
// qwarp^(2^k) (uniform). qlane = q^lane (per-lane). qwid = qwarp^wid
// (per-warp). qblk = qwarp^NWARPS (uniform). carry: replicated resolved
// value entering this chunk. All threads hold full RPT samples (tail chunk
// is zero-padded), so every aggregate's decay is position-deterministic.
template <bool MAXOP>
__device__ __forceinline__ void scan8(const float* in, float* out,
                                      float alpha, float om,
                                      const float* qpow, const float* qwpow,
                                      float qlane, float qwid, float qblk,
                                      float& carry, float2* sw,
                                      int lane, int wid)
{
    // Phase 1: per-thread running linear response v and local envelope yl.
    float v = om * in[0];
    float yl = in[0];
    out[0] = yl;
    #pragma unroll
    for (int j = 1; j < RPT; j++) {
        float omm = om * in[j];
        v  = fmaf(alpha, v, omm);
        yl = sel<MAXOP>(in[j], fmaf(alpha, yl, omm));
        out[j] = yl;
    }

    // Warp Kogge-Stone over thread aggregates (U, V); A implicit & uniform.
    float U = yl, V = v;
    #pragma unroll
    for (int k = 0; k < 5; k++) {
        const int d = 1 << k;
        float uU = __shfl_up_sync(0xffffffffu, U, d);
        float uV = __shfl_up_sync(0xffffffffu, V, d);
        const float bA = qpow[k];            // uniform: q^(2^k)
        if (lane >= d) {
            U = sel<MAXOP>(U, fmaf(bA, uU, V));
            V = fmaf(bA, uV, V);
        }
    }
    // Thread-exclusive (within warp): value at lane-1; A = q^lane implicit.
    float Ue = __shfl_up_sync(0xffffffffu, U, 1);
    float Ve = __shfl_up_sync(0xffffffffu, V, 1);

    if (lane == 31) sw[wid] = make_float2(U, V);
    __syncthreads();

    // Cross-warp scan over NWARPS aggregates, redundant in every warp.
    float cU = MAXOP ? -FLT_MAX : FLT_MAX, cV = 0.0f;
    if (lane < NWARPS) { float2 t = sw[lane]; cU = t.x; cV = t.y; }
    #pragma unroll
    for (int k = 0; k < 4; k++) {            // NWARPS = 16 -> 4 steps
        const int d = 1 << k;
        float uU = __shfl_up_sync(0xffffffffu, cU, d);
        float uV = __shfl_up_sync(0xffffffffu, cV, d);
        const float bA = qwpow[k];           // uniform: qwarp^(2^k)
        if (lane >= d) {
            cU = sel<MAXOP>(cU, fmaf(bA, uU, cV));
            cV = fmaf(bA, uV, cV);
        }
    }

    // Warp-incoming resolved value: apply exclusive-over-warps to carry.
    const int src = (wid == 0) ? 0 : (wid - 1);
    float WU = __shfl_sync(0xffffffffu, cU, src);
    float WV = __shfl_sync(0xffffffffu, cV, src);
    float c_w = (wid == 0) ? carry : sel<MAXOP>(WU, fmaf(qwid, carry, WV));

    // Block total (lane NWARPS-1) for the carry update.
    float TU = __shfl_sync(0xffffffffu, cU, NWARPS - 1);
    float TV = __shfl_sync(0xffffffffu, cV, NWARPS - 1);
    float ncar = sel<MAXOP>(TU, fmaf(qblk, carry, TV));

    // Thread-incoming resolved value.
    float c = (lane == 0) ? c_w : sel<MAXOP>(Ue, fmaf(qlane, c_w, Ve));

    // Fixup: linear recurrence seeded with c; out = op(local, z).
    float z = c;
    #pragma unroll
    for (int j = 0; j < RPT; j++) {
        z = fmaf(alpha, z, om * in[j]);
        out[j] = sel<MAXOP>(out[j], z);
    }
    carry = ncar;
}

__global__ void __launch_bounds__(THREADS, 2)
tce_kernel(const float* __restrict__ x,
           const float* __restrict__ p_tauA,
           const float* __restrict__ p_tauD,
           const float* __restrict__ p_nu,
           const float* __restrict__ p_dbr,
           float* __restrict__ out, int T)
{
    __shared__ float2 swb[3][NWARPS];

    const int lane = threadIdx.x & 31;
    const int wid  = threadIdx.x >> 5;
    const long long ch = blockIdx.x;
    const float* xc = x + ch * (long long)T;
    float* oc = out + ch * (long long)T;

    // Scalar params (replicate reference clip chain)
    float tauA = fminf(fmaxf(p_tauA[0], 1.0f), 100.0f);
    tauA = fminf(fmaxf(tauA, 0.1f), 1000.0f) * 0.001f;
    const float aa = expf(-1.0f / (tauA * 44100.0f));
    float tauD = fminf(fmaxf(p_tauD[0], 1.0f), 100.0f);
    tauD = fminf(fmaxf(tauD, 0.1f), 1000.0f) * 0.001f;
    const float ad = expf(-1.0f / (tauD * 44100.0f));
    const float nuAmp = exp10f(fminf(fmaxf(p_nu[0], -60.0f), 0.0f) * 0.05f);
    const float reg   = exp10f(fminf(fmaxf(p_dbr[0], -120.0f), -60.0f) * 0.05f);
    const float omd = 1.0f - ad;
    const float oma = 1.0f - aa;

    // q = alpha^8 (3 squarings); qpow[k] = q^(2^k); qwarp = q^32;
    // qwpow[k] = qwarp^(2^k); qblk = qwarp^16. All uniform.
    float qd = ad * ad; qd *= qd; qd *= qd;     // ad^8
    float qa = aa * aa; qa *= qa; qa *= qa;     // aa^8
    float qdpow[5], qapow[5];
    qdpow[0] = qd; qapow[0] = qa;
    #pragma unroll
    for (int k = 1; k < 5; k++) {
        qdpow[k] = qdpow[k - 1] * qdpow[k - 1];
        qapow[k] = qapow[k - 1] * qapow[k - 1];
    }
    float qwdpow[4], qwapow[4];
    qwdpow[0] = qdpow[4] * qdpow[4];            // q^32
    qwapow[0] = qapow[4] * qapow[4];
    #pragma unroll
    for (int k = 1; k < 4; k++) {
        qwdpow[k] = qwdpow[k - 1] * qwdpow[k - 1];
        qwapow[k] = qwapow[k - 1] * qwapow[k - 1];
    }
    const float qblkd = qwdpow[3] * qwdpow[3];  // qwarp^16 = alpha^4096
    const float qblka = qwapow[3] * qwapow[3];

    // Per-lane q^lane, per-warp qwarp^wid (init-only loops).
    float qdlane = 1.0f, qalane = 1.0f;
    for (int i = 0; i < lane; i++) { qdlane *= qd; qalane *= qa; }
    float qwidd = 1.0f, qwida = 1.0f;
    for (int i = 0; i < wid; i++) { qwidd *= qwdpow[0]; qwida *= qwapow[0]; }

    float cd = 0.0f, ca = 0.0f, ce = 0.0f;   // carries

    for (int base = 0; base < T; base += CHUNK) {
        const int off = base + (int)threadIdx.x * RPT;
        float A_[RPT], B_[RPT];

        // Load |x| (zero-padded beyond T; tail chunk only)
        #pragma unroll
        for (int g = 0; g < RPT / 4; g++) {
            const int o = off + g * 4;
            float4 v = make_float4(0.f, 0.f, 0.f, 0.f);
            if (o + 4 <= T) {
                v = *reinterpret_cast<const float4*>(xc + o);
            } else if (o < T) {
                v.x = xc[o];
                if (o + 1 < T) v.y = xc[o + 1];
                if (o + 2 < T) v.z = xc[o + 2];
            }
            A_[4 * g + 0] = fabsf(v.x);
            A_[4 * g + 1] = fabsf(v.y);
            A_[4 * g + 2] = fabsf(v.z);
            A_[4 * g + 3] = fabsf(v.w);
        }

        // et_d = envd(|x|)   (max, alpha_d):  A_ -> B_
        scan8<true >(A_, B_, ad, omd, qdpow, qwdpow, qdlane, qwidd, qblkd,
                     cd, swb[0], lane, wid);
        // et_a = enva(et_d)  (min, alpha_a):  B_ -> A_
        scan8<false>(B_, A_, aa, oma, qapow, qwapow, qalane, qwida, qblka,
                     ca, swb[1], lane, wid);
        // et = relu(et_d - et_a - nuAmp)   -> A_
        #pragma unroll
        for (int j = 0; j < RPT; j++)
            A_[j] = fmaxf(B_[j] - A_[j] - nuAmp, 0.0f);
        // et_env = envd(et)  (max, alpha_d):  A_ -> B_
        scan8<true >(A_, B_, ad, omd, qdpow, qwdpow, qdlane, qwidd, qblkd,
                     ce, swb[2], lane, wid);

        // out = x * et / (et_env + reg)   (x reloaded; L1/L2-hot)
        #pragma unroll
        for (int g = 0; g < RPT / 4; g++) {
            const int o = off + g * 4;
            if (o + 4 <= T) {
                float4 xv = *reinterpret_cast<const float4*>(xc + o);
                float4 r;
                r.x = xv.x * __fdividef(A_[4 * g + 0], B_[4 * g + 0] + reg);
                r.y = xv.y * __fdividef(A_[4 * g + 1], B_[4 * g + 1] + reg);
                r.z = xv.z * __fdividef(A_[4 * g + 2], B_[4 * g + 2] + reg);
                r.w = xv.w * __fdividef(A_[4 * g + 3], B_[4 * g + 3] + reg);
                *reinterpret_cast<float4*>(oc + o) = r;
            } else if (o < T) {
                oc[o] = xc[o] * __fdividef(A_[4 * g + 0], B_[4 * g + 0] + reg);
                if (o + 1 < T)
                    oc[o + 1] = xc[o + 1] * __fdividef(A_[4 * g + 1], B_[4 * g + 1] + reg);
                if (o + 2 < T)
                    oc[o + 2] = xc[o + 2] * __fdividef(A_[4 * g + 2], B_[4 * g + 2] + reg);
            }
        }
    }
}

extern "C" void kernel_launch(void* const* d_in, const int* in_sizes, int n_in,
                              void* d_out, int out_size)
{
    const float* x      = (const float*)d_in[0];
    const float* tauAtc = (const float*)d_in[1];
    const float* tauDtc = (const float*)d_in[2];
    const float* nu     = (const float*)d_in[3];
    const float* dbr    = (const float*)d_in[4];
    float* out = (float*)d_out;

    const int T = T_LEN;
    const int channels = in_sizes[0] / T;   // 256

    tce_kernel<<<channels, THREADS>>>(x, tauAtc, tauDtc, nu, dbr, out, T);
}